// round 14
// baseline (speedup 1.0000x reference)
#include <cuda_runtime.h>
#include <cuda_fp16.h>
#include <cstdint>
#include <math.h>

// ============================================================================
// NeRF fused MLP via mma.sync (HMMA f16), single-term fp16, warp-private
// weight pipelines (ZERO intra-layer barriers).
// CTA = 64 rows, 256 threads (8 warps), ~83 KB SMEM, 2 CTAs/SM.
// Each warp owns a 32-col N strip (views: 16-col) over ALL 64 rows:
//   acc[4 mt][4 n8][4], chunk = 32 k-rows. Warp double-buffers its own
//   2 KB W slice via cp.async + wait_group + __syncwarp. __syncthreads only
//   at layer boundaries (A-plane rewrite).
// A fp16 plane [64][360]: cols 0..83 e_pts (pad->95), 96..351 h.
// Output: d_out[0..N) = alpha, d_out[N..4N) = rgb row-major [N,3].
// ============================================================================

#define NPTS  131072
#define NTH   256
#define NBLK  (NPTS / 64)
#define NCHTOT 80

// ---- smem byte offsets -------------------------------------------------------
#define A_HI    0u
#define ASTR    720u         // 360 fp16 per row
#define SLB     46080u       // W slices: 8 warps x 2 bufs x 2304 B = 36864
#define WGSTR   4608u        // per-warp slice pair
#define BUFSTR  2304u
#define SSTR    144u         // slice row stride (16 rows x 128B data + pad)
#define ALPHA_P 82944u       // alpha partials: 64 rows x 8 warps x 4 B = 2048
#define PRGB    46080u       // rgb partials overlay slices (after views layer)
#define SMEM_REQ 84992
#define CHB     16896u       // bytes per weight chunk in g_wbuf (32 x 528)
#define WSTRG   528u         // g_wbuf row stride (264 fp16)

__device__ __align__(16) __half g_wbuf[675840];   // 80 * 8448 halfs

// ---- helpers -------------------------------------------------------------------
__device__ __forceinline__ uint32_t smem_u32(const void* p) {
    uint32_t a;
    asm("{ .reg .u64 t; cvta.to.shared.u64 t, %1; cvt.u32.u64 %0, t; }"
        : "=r"(a) : "l"(p));
    return a;
}
__device__ __forceinline__ void cp_async16(uint32_t saddr, const void* g) {
    asm volatile("cp.async.cg.shared.global [%0], [%1], 16;" :: "r"(saddr), "l"(g));
}
__device__ __forceinline__ void cp_commit() { asm volatile("cp.async.commit_group;"); }
__device__ __forceinline__ void cp_wait1() {
    asm volatile("cp.async.wait_group 1;" ::: "memory");
}
__device__ __forceinline__ void ldm4(uint32_t d[4], uint32_t a) {
    asm volatile("ldmatrix.sync.aligned.m8n8.x4.shared.b16 {%0,%1,%2,%3}, [%4];"
        : "=r"(d[0]), "=r"(d[1]), "=r"(d[2]), "=r"(d[3]) : "r"(a));
}
__device__ __forceinline__ void ldm4t(uint32_t d[4], uint32_t a) {
    asm volatile("ldmatrix.sync.aligned.m8n8.x4.trans.shared.b16 {%0,%1,%2,%3}, [%4];"
        : "=r"(d[0]), "=r"(d[1]), "=r"(d[2]), "=r"(d[3]) : "r"(a));
}
__device__ __forceinline__ void mma16816(float c[4], const uint32_t a[4],
                                         uint32_t b0, uint32_t b1) {
    asm volatile("mma.sync.aligned.m16n8k16.row.col.f32.f16.f16.f32 "
        "{%0,%1,%2,%3}, {%4,%5,%6,%7}, {%8,%9}, {%0,%1,%2,%3};"
        : "+f"(c[0]), "+f"(c[1]), "+f"(c[2]), "+f"(c[3])
        : "r"(a[0]), "r"(a[1]), "r"(a[2]), "r"(a[3]), "r"(b0), "r"(b1));
}
__device__ __forceinline__ uint32_t pack_h2(float a, float b) {
    __half2 t = __floats2half2_rn(a, b);
    return *reinterpret_cast<uint32_t*>(&t);
}

// ============================================================================
// prep: fp32 weights -> fp16, K-padded, chunk-sequential [k32][264] planes
// chunk order: L0(3) L1..L4(8 ea) L5(11) L6(8) L7(8) feat(8) views(10) = 80
// ============================================================================
struct PrepP { const float* w[10]; };   // pw0..7, feature_w, views_w

__global__ void prep_kernel(PrepP pp) {
    const int cum[11] = {0,3,11,19,27,35,46,54,62,70,80};
    for (unsigned e = blockIdx.x * blockDim.x + threadIdx.x; e < 675840u;
         e += gridDim.x * blockDim.x) {
        unsigned g = e / 8448u, rem = e - g * 8448u;
        unsigned r = rem / 264u, c = rem - r * 264u;
        int l = 9;
        for (int i = 1; i <= 9; i++) { if ((int)g < cum[i]) { l = i - 1; break; } }
        int krow = (int)(g - cum[l]) * 32 + (int)r;
        int N = (l == 9) ? 128 : 256;
        int sr = krow;
        if (l == 0)      sr = (krow < 84)  ? krow : -1;
        else if (l == 5) sr = (krow < 84)  ? krow : (krow < 96 ? -1 : krow - 12);
        else if (l == 9) sr = (krow < 310) ? krow : -1;
        float v = 0.f;
        if (sr >= 0 && (int)c < N) v = pp.w[l][(size_t)sr * N + c];
        g_wbuf[(size_t)g * 8448u + r * 264u + c] = __float2half_rn(v);
    }
}

// ============================================================================
// warp-private slice loader: chunk g's strip -> my slice buffer b
//   WIDE=1: 32 cols (64B/row), rows packed 2-wide: (r&15)*SSTR + (r>>4)*64
//   WIDE=0: 16 cols (32B/row): (r&15)*SSTR + (r>>4)*32
// ============================================================================
template<int WIDE>
__device__ __forceinline__ void load_slice(uint32_t myslice, int wn8, int lane,
                                           int g, int b) {
    const char* gsrc = (const char*)g_wbuf + (size_t)g * CHB
                     + (unsigned)wn8 * (WIDE ? 64u : 32u);
    uint32_t dst = myslice + (unsigned)b * BUFSTR;
    if (WIDE) {
        #pragma unroll
        for (int j = 0; j < 4; j++) {
            unsigned idx = (unsigned)lane + j * 32u;       // 0..127
            unsigned r = idx >> 2, seg = (idx & 3u) * 16u;
            cp_async16(dst + (r & 15u) * SSTR + (r >> 4) * 64u + seg,
                       gsrc + r * WSTRG + seg);
        }
    } else {
        #pragma unroll
        for (int j = 0; j < 2; j++) {
            unsigned idx = (unsigned)lane + j * 32u;       // 0..63
            unsigned r = idx >> 1, seg = (idx & 1u) * 16u;
            cp_async16(dst + (r & 15u) * SSTR + (r >> 4) * 32u + seg,
                       gsrc + r * WSTRG + seg);
        }
    }
}

// ============================================================================
// chunk compute: acc += A[64, k32] * Wslice[k32, 32|16]
// ============================================================================
template<int N8>
__device__ __forceinline__ void chunk_mma(uint32_t base32, uint32_t wslice,
                                          int lane, int kcol,
                                          float acc[4][4][4]) {
    #pragma unroll
    for (int ks = 0; ks < 2; ks++) {
        const uint32_t acol = (uint32_t)(kcol + ks * 16) + (uint32_t)((lane >> 4) << 3);
        uint32_t ah[4][4];
        #pragma unroll
        for (int mt = 0; mt < 4; mt++) {
            uint32_t ar = (uint32_t)(mt * 16 + (lane & 15));
            ldm4(ah[mt], base32 + A_HI + ar * ASTR + acol * 2u);
        }
        uint32_t wb = wslice + (uint32_t)(lane & 15) * SSTR
                    + (uint32_t)(ks * (N8 == 4 ? 64 : 32))
                    + (uint32_t)((lane >> 4) << 3) * 2u;
        uint32_t b[N8 / 2][4];
        #pragma unroll
        for (int g2 = 0; g2 < N8 / 2; g2++) ldm4t(b[g2], wb + g2 * 32u);
        #pragma unroll
        for (int mt = 0; mt < 4; mt++)
            #pragma unroll
            for (int n8 = 0; n8 < N8; n8++)
                mma16816(acc[mt][n8], ah[mt],
                         b[n8 >> 1][(n8 & 1) * 2], b[n8 >> 1][(n8 & 1) * 2 + 1]);
    }
}

// ============================================================================
struct MainP {
    const float *input_pts, *input_views, *input_pls;
    const float *bias[9];          // pb0..7, feature_b
    const float *views_b;
    const float *alpha_w, *alpha_b;
    const float *rgb_w, *rgb_b;
    float* out;
};

extern __shared__ char smdyn[];

__global__ void __launch_bounds__(NTH, 2) nerf_hmma(MainP P) {
    char* sm = smdyn;
    const uint32_t base32 = smem_u32(sm);
    const int tid = threadIdx.x, lane = tid & 31, wn8 = tid >> 5;  // warp = N strip
    const int blk = blockIdx.x;
    const uint32_t myslice = base32 + SLB + (uint32_t)wn8 * WGSTR;

    // prologue: every warp prefetches its chunk-0 strip
    load_slice<1>(myslice, wn8, lane, 0, 0);
    cp_commit();

    // e_pts build: cols 0..83, pad 84..95 zero (64 rows)
    if (tid < 64) {
        size_t gidx = (size_t)blk * 64 + tid;
        float4 p4 = *reinterpret_cast<const float4*>(P.input_pts + gidx * 4);
        float xs[4] = {p4.x, p4.y, p4.z, p4.w};
        float vals[96];
        #pragma unroll
        for (int d = 0; d < 4; d++) vals[d] = xs[d];
        #pragma unroll
        for (int d = 0; d < 4; d++) {
            float f = 1.f;
            #pragma unroll
            for (int l = 0; l < 10; l++) {
                float sn, cs; sincosf(xs[d] * f, &sn, &cs);
                vals[4 + d * 20 + l * 2]     = sn;
                vals[4 + d * 20 + l * 2 + 1] = cs;
                f *= 2.f;
            }
        }
        #pragma unroll
        for (int k = 84; k < 96; k++) vals[k] = 0.f;
        char* rh = sm + A_HI + (uint32_t)tid * ASTR;
        #pragma unroll 4
        for (int k = 0; k < 96; k += 2)
            *(uint32_t*)(rh + k * 2) = pack_h2(vals[k], vals[k + 1]);
    }
    __syncthreads();

    const int L_koff[9] = {0, 96, 96, 96, 96, 0, 96, 96, 96};
    const int L_nch[9]  = {3, 8, 8, 8, 8, 11, 8, 8, 8};
    float acc[4][4][4];
    int g = 0;

    #pragma unroll 1
    for (int l = 0; l < 9; l++) {
        #pragma unroll
        for (int mt = 0; mt < 4; mt++)
            #pragma unroll
            for (int n8 = 0; n8 < 4; n8++)
                #pragma unroll
                for (int q = 0; q < 4; q++) acc[mt][n8][q] = 0.f;

        const int koff = L_koff[l], nch = L_nch[l];
        #pragma unroll 1
        for (int ch = 0; ch < nch; ch++) {
            // warp-private pipeline: prefetch g+1, wait for g, no barriers
            if (g + 1 < NCHTOT) {
                if (g + 1 >= 70) load_slice<0>(myslice, wn8, lane, g + 1, (g + 1) & 1);
                else             load_slice<1>(myslice, wn8, lane, g + 1, (g + 1) & 1);
            }
            cp_commit();
            cp_wait1();
            __syncwarp();
            chunk_mma<4>(base32, myslice + (uint32_t)(g & 1) * BUFSTR,
                         lane, koff + ch * 32, acc);
            g++;
        }
        __syncthreads();                         // all MMA reads of A done

        // ---- epilogue: bias (+relu) (+alpha) -> fp16 -> A plane --------------
        // warp owns cols wn8*32 .. +32, all 64 rows.
        const bool relu = (l != 8);
        const uint32_t colbase = (l == 8) ? 0u : 96u;
        const float* bias = P.bias[l];
        float ap[4][2];
        #pragma unroll
        for (int mt = 0; mt < 4; mt++) { ap[mt][0] = 0.f; ap[mt][1] = 0.f; }
        #pragma unroll
        for (int mt = 0; mt < 4; mt++) {
            #pragma unroll
            for (int half = 0; half < 2; half++) {
                const uint32_t row = (uint32_t)(mt * 16 + half * 8 + (lane >> 2));
                char* rh = sm + A_HI + row * ASTR + colbase * 2u;
                #pragma unroll
                for (int n8 = 0; n8 < 4; n8++) {
                    const int col = wn8 * 32 + n8 * 8 + (lane & 3) * 2;
                    float2 bv = *(const float2*)(bias + col);
                    float f0 = acc[mt][n8][half * 2]     + bv.x;
                    float f1 = acc[mt][n8][half * 2 + 1] + bv.y;
                    if (relu) { f0 = fmaxf(f0, 0.f); f1 = fmaxf(f1, 0.f); }
                    if (l == 7) {
                        float2 aw = *(const float2*)(P.alpha_w + col);
                        ap[mt][half] += f0 * aw.x + f1 * aw.y;
                    }
                    *(uint32_t*)(rh + col * 2) = pack_h2(f0, f1);
                }
            }
        }
        if (l == 7) {        // alpha partials -> ALPHA_P [row][warp]
            #pragma unroll
            for (int mt = 0; mt < 4; mt++)
                #pragma unroll
                for (int half = 0; half < 2; half++) {
                    float v = ap[mt][half];
                    v += __shfl_xor_sync(0xffffffffu, v, 1);
                    v += __shfl_xor_sync(0xffffffffu, v, 2);
                    if ((lane & 3) == 0) {
                        uint32_t row = (uint32_t)(mt * 16 + half * 8 + (lane >> 2));
                        *(float*)(sm + ALPHA_P + (row * 8u + (uint32_t)wn8) * 4u) = v;
                    }
                }
            __syncthreads();
            if (tid < 64) {
                char* rp = sm + ALPHA_P + (uint32_t)tid * 32u;
                float a = P.alpha_b[0];
                #pragma unroll
                for (int w = 0; w < 8; w++) a += *(float*)(rp + w * 4);
                P.out[(size_t)blk * 64 + tid] = a;
            }
        }
        if (l == 8 && tid < 64) {    // e_view into cols 256..319 (310..319 zero)
            size_t gidx = (size_t)blk * 64 + tid;
            float xs[6];
            xs[0] = P.input_views[gidx * 3];     xs[1] = P.input_views[gidx * 3 + 1];
            xs[2] = P.input_views[gidx * 3 + 2]; xs[3] = P.input_pls[gidx * 3];
            xs[4] = P.input_pls[gidx * 3 + 1];   xs[5] = P.input_pls[gidx * 3 + 2];
            float vals[64];
            #pragma unroll
            for (int d = 0; d < 6; d++) vals[d] = xs[d];
            #pragma unroll
            for (int d = 0; d < 6; d++) {
                float f = 1.f;
                #pragma unroll
                for (int q = 0; q < 4; q++) {
                    float sn, cs; sincosf(xs[d] * f, &sn, &cs);
                    vals[6 + d * 8 + q * 2]     = sn;
                    vals[6 + d * 8 + q * 2 + 1] = cs;
                    f *= 2.f;
                }
            }
            #pragma unroll
            for (int k = 54; k < 64; k++) vals[k] = 0.f;
            char* rh = sm + A_HI + (uint32_t)tid * ASTR + 256u * 2u;
            #pragma unroll 4
            for (int k = 0; k < 64; k += 2)
                *(uint32_t*)(rh + k * 2) = pack_h2(vals[k], vals[k + 1]);
        }
        __syncthreads();                         // A rewrite visible to all
    }

    // ---- views layer: K=320, N=128; warp owns 16 cols (10 chunks) -------------
    #pragma unroll
    for (int mt = 0; mt < 4; mt++)
        #pragma unroll
        for (int n8 = 0; n8 < 2; n8++)
            #pragma unroll
            for (int q = 0; q < 4; q++) acc[mt][n8][q] = 0.f;
    #pragma unroll 1
    for (int ch = 0; ch < 10; ch++) {
        if (g + 1 < NCHTOT) load_slice<0>(myslice, wn8, lane, g + 1, (g + 1) & 1);
        cp_commit();
        cp_wait1();
        __syncwarp();
        chunk_mma<2>(base32, myslice + (uint32_t)(g & 1) * BUFSTR,
                     lane, ch * 32, acc);
        g++;
    }
    __syncthreads();                             // slices dead -> PRGB overlay ok

    // ---- rgb head: relu(C + views_b) . rgb_w, fp32 ----------------------------
    float rp[4][2][3];
    #pragma unroll
    for (int mt = 0; mt < 4; mt++)
        #pragma unroll
        for (int half = 0; half < 2; half++)
            #pragma unroll
            for (int k = 0; k < 3; k++) rp[mt][half][k] = 0.f;
    #pragma unroll
    for (int mt = 0; mt < 4; mt++)
        #pragma unroll
        for (int half = 0; half < 2; half++)
            #pragma unroll
            for (int n8 = 0; n8 < 2; n8++) {
                const int col = wn8 * 16 + n8 * 8 + (lane & 3) * 2;
                float f0 = fmaxf(acc[mt][n8][half * 2]     + P.views_b[col],     0.f);
                float f1 = fmaxf(acc[mt][n8][half * 2 + 1] + P.views_b[col + 1], 0.f);
                const float* w0 = P.rgb_w + (size_t)col * 3;
                #pragma unroll
                for (int k = 0; k < 3; k++)
                    rp[mt][half][k] += f0 * w0[k] + f1 * w0[3 + k];
            }
    #pragma unroll
    for (int mt = 0; mt < 4; mt++)
        #pragma unroll
        for (int half = 0; half < 2; half++) {
            #pragma unroll
            for (int k = 0; k < 3; k++) {
                float v = rp[mt][half][k];
                v += __shfl_xor_sync(0xffffffffu, v, 1);
                v += __shfl_xor_sync(0xffffffffu, v, 2);
                rp[mt][half][k] = v;
            }
            if ((lane & 3) == 0) {
                uint32_t row = (uint32_t)(mt * 16 + half * 8 + (lane >> 2));
                char* p = sm + PRGB + (row * 8u + (uint32_t)wn8) * 12u;
                #pragma unroll
                for (int k = 0; k < 3; k++) *(float*)(p + k * 4) = rp[mt][half][k];
            }
        }
    __syncthreads();
    if (tid < 64) {
        float r[3] = {P.rgb_b[0], P.rgb_b[1], P.rgb_b[2]};
        char* p = sm + PRGB + (uint32_t)tid * 96u;
        #pragma unroll
        for (int w = 0; w < 8; w++)
            #pragma unroll
            for (int k = 0; k < 3; k++) r[k] += *(float*)(p + w * 12 + k * 4);
        size_t gidx = (size_t)blk * 64 + tid;
        #pragma unroll
        for (int k = 0; k < 3; k++) P.out[(size_t)NPTS + gidx * 3 + k] = r[k];
    }
}

// ============================================================================
extern "C" void kernel_launch(void* const* d_in, const int* in_sizes, int n_in,
                              void* d_out, int out_size)
{
    (void)in_sizes; (void)n_in; (void)out_size;

    PrepP pp;
    for (int i = 0; i < 8; i++) pp.w[i] = (const float*)d_in[3 + 2 * i];
    pp.w[8] = (const float*)d_in[21];     // feature_w
    pp.w[9] = (const float*)d_in[19];     // views_w

    MainP P;
    P.input_pts   = (const float*)d_in[0];
    P.input_views = (const float*)d_in[1];
    P.input_pls   = (const float*)d_in[2];
    for (int i = 0; i < 8; i++) P.bias[i] = (const float*)d_in[4 + 2 * i];
    P.bias[8]  = (const float*)d_in[22];  // feature_b
    P.views_b  = (const float*)d_in[20];
    P.alpha_w  = (const float*)d_in[23];
    P.alpha_b  = (const float*)d_in[24];
    P.rgb_w    = (const float*)d_in[25];
    P.rgb_b    = (const float*)d_in[26];
    P.out      = (float*)d_out;

    prep_kernel<<<1320, 512>>>(pp);

    cudaFuncSetAttribute(nerf_hmma, cudaFuncAttributeMaxDynamicSharedMemorySize, SMEM_REQ);
    nerf_hmma<<<NBLK, NTH, SMEM_REQ>>>(P);
}

// round 15
// speedup vs baseline: 1.0263x; 1.0263x over previous
#include <cuda_runtime.h>
#include <cuda_fp16.h>
#include <cstdint>
#include <math.h>

// ============================================================================
// NeRF fused MLP via mma.sync (HMMA f16), single-term fp16:
//   x*w ~= fp16(x)*fp16(w), fp32 accum.
// CTA = 64 rows, 256 threads (8 warps), ~99 KB SMEM, 2 CTAs/SM.
//   wn = wid>>1 (N quarter / group, 2 warps), wm = wid&1 (row half).
// Per-group TRIPLE-buffered 64-col W slices per 32-k-row chunk (loader =
// wm==0 warp, prefetch distance 2) + named barriers. A fp16 plane [64][360]:
//   cols 0..83 e_pts (pad->95), 96..351 h -> skip concat free.
// Output: d_out[0..N) = alpha, d_out[N..4N) = rgb row-major [N,3].
// ============================================================================

#define NPTS  131072
#define NTH   256
#define NBLK  (NPTS / 64)
#define NCHTOT 80

// ---- smem byte offsets -------------------------------------------------------
#define A_HI   0u
#define ASTR   720u          // 360 fp16 per row (704 data + 16 pad for alpha)
#define APAD   704u
#define SLB    46080u        // W slices: 4 groups x 3 bufs x 4608 B
#define GRPSTR 13824u
#define BUFSTR 4608u
#define SSTR   144u          // slice row stride (conflict-free ldmatrix)
#define PRGB   46080u        // rgb partials overlay slices (after full sync)
#define SMEM_REQ 101376
#define CHB    16896u        // bytes per weight chunk: 32 rows x 528 B
#define WSTRG  528u          // g_wbuf row stride (264 fp16)

__device__ __align__(16) __half g_wbuf[675840];   // 80 * 8448 halfs

// ---- helpers -------------------------------------------------------------------
__device__ __forceinline__ uint32_t smem_u32(const void* p) {
    uint32_t a;
    asm("{ .reg .u64 t; cvta.to.shared.u64 t, %1; cvt.u32.u64 %0, t; }"
        : "=r"(a) : "l"(p));
    return a;
}
__device__ __forceinline__ void cp_async16(uint32_t saddr, const void* g) {
    asm volatile("cp.async.cg.shared.global [%0], [%1], 16;" :: "r"(saddr), "l"(g));
}
__device__ __forceinline__ void cp_commit() { asm volatile("cp.async.commit_group;"); }
__device__ __forceinline__ void cp_wait2() {
    asm volatile("cp.async.wait_group 2;" ::: "memory");
}
__device__ __forceinline__ void named_bar(int id) {
    asm volatile("bar.sync %0, 64;" :: "r"(id) : "memory");
}
__device__ __forceinline__ void ldm4(uint32_t d[4], uint32_t a) {
    asm volatile("ldmatrix.sync.aligned.m8n8.x4.shared.b16 {%0,%1,%2,%3}, [%4];"
        : "=r"(d[0]), "=r"(d[1]), "=r"(d[2]), "=r"(d[3]) : "r"(a));
}
__device__ __forceinline__ void ldm4t(uint32_t d[4], uint32_t a) {
    asm volatile("ldmatrix.sync.aligned.m8n8.x4.trans.shared.b16 {%0,%1,%2,%3}, [%4];"
        : "=r"(d[0]), "=r"(d[1]), "=r"(d[2]), "=r"(d[3]) : "r"(a));
}
__device__ __forceinline__ void mma16816(float c[4], const uint32_t a[4],
                                         uint32_t b0, uint32_t b1) {
    asm volatile("mma.sync.aligned.m16n8k16.row.col.f32.f16.f16.f32 "
        "{%0,%1,%2,%3}, {%4,%5,%6,%7}, {%8,%9}, {%0,%1,%2,%3};"
        : "+f"(c[0]), "+f"(c[1]), "+f"(c[2]), "+f"(c[3])
        : "r"(a[0]), "r"(a[1]), "r"(a[2]), "r"(a[3]), "r"(b0), "r"(b1));
}
__device__ __forceinline__ uint32_t pack_h2(float a, float b) {
    __half2 t = __floats2half2_rn(a, b);
    return *reinterpret_cast<uint32_t*>(&t);
}

// ============================================================================
// prep: fp32 weights -> fp16, K-padded, chunk-sequential [k32][264] planes
// chunk order: L0(3) L1..L4(8 ea) L5(11) L6(8) L7(8) feat(8) views(10) = 80
// ============================================================================
struct PrepP { const float* w[10]; };   // pw0..7, feature_w, views_w

__global__ void prep_kernel(PrepP pp) {
    const int cum[11] = {0,3,11,19,27,35,46,54,62,70,80};
    for (unsigned e = blockIdx.x * blockDim.x + threadIdx.x; e < 675840u;
         e += gridDim.x * blockDim.x) {
        unsigned g = e / 8448u, rem = e - g * 8448u;
        unsigned r = rem / 264u, c = rem - r * 264u;
        int l = 9;
        for (int i = 1; i <= 9; i++) { if ((int)g < cum[i]) { l = i - 1; break; } }
        int krow = (int)(g - cum[l]) * 32 + (int)r;
        int N = (l == 9) ? 128 : 256;
        int sr = krow;
        if (l == 0)      sr = (krow < 84)  ? krow : -1;
        else if (l == 5) sr = (krow < 84)  ? krow : (krow < 96 ? -1 : krow - 12);
        else if (l == 9) sr = (krow < 310) ? krow : -1;
        float v = 0.f;
        if (sr >= 0 && (int)c < N) v = pp.w[l][(size_t)sr * N + c];
        g_wbuf[(size_t)g * 8448u + r * 264u + c] = __float2half_rn(v);
    }
}

// ============================================================================
// per-group slice loader: chunk g's wn-strip (32 k-rows) -> slice buffer b
// ============================================================================
template<int N8>
__device__ __forceinline__ void load_slice(uint32_t base32, int wn, int lane,
                                           int g, int b) {
    const char* gsrc = (const char*)g_wbuf + (size_t)g * CHB
                     + (unsigned)wn * (N8 == 8 ? 128u : 64u);
    uint32_t dst = base32 + SLB + (unsigned)wn * GRPSTR + (unsigned)b * BUFSTR;
    if (N8 == 8) {        // 64 cols = 128 B/row, 32 rows -> 256 x 16B
        #pragma unroll
        for (int j = 0; j < 8; j++) {
            unsigned idx = (unsigned)lane + j * 32u;
            unsigned r = idx >> 3, c16 = (idx & 7u) * 16u;
            cp_async16(dst + r * SSTR + c16, gsrc + r * WSTRG + c16);
        }
    } else {              // 32 cols = 64 B/row -> 128 x 16B
        #pragma unroll
        for (int j = 0; j < 4; j++) {
            unsigned idx = (unsigned)lane + j * 32u;
            unsigned r = idx >> 2, c16 = (idx & 3u) * 16u;
            cp_async16(dst + r * SSTR + c16, gsrc + r * WSTRG + c16);
        }
    }
}

// ============================================================================
// chunk compute: acc += A[64, k32] * Wslice[k32, 64|32]   (single-term fp16)
// ============================================================================
template<int N8>
__device__ __forceinline__ void chunk_mma(uint32_t base32, uint32_t wslice,
                                          int wm, int lane,
                                          int kcol, float acc[2][8][4]) {
    #pragma unroll
    for (int ks = 0; ks < 2; ks++) {
        const uint32_t arow = (uint32_t)(wm * 32 + (lane & 15));
        const uint32_t acol = (uint32_t)(kcol + ks * 16) + (uint32_t)((lane >> 4) << 3);
        uint32_t a0 = base32 + A_HI + arow * ASTR + acol * 2u;
        uint32_t a1 = a0 + 16u * ASTR;
        uint32_t ah[2][4], b[N8 / 2][4];
        ldm4(ah[0], a0); ldm4(ah[1], a1);
        uint32_t wb = wslice + (uint32_t)(ks * 16 + (lane & 15)) * SSTR
                    + (uint32_t)((lane >> 4) << 3) * 2u;
        #pragma unroll
        for (int g2 = 0; g2 < N8 / 2; g2++) ldm4t(b[g2], wb + g2 * 32u);
        #pragma unroll
        for (int mt = 0; mt < 2; mt++)
            #pragma unroll
            for (int n8 = 0; n8 < N8; n8++)
                mma16816(acc[mt][n8], ah[mt],
                         b[n8 >> 1][(n8 & 1) * 2], b[n8 >> 1][(n8 & 1) * 2 + 1]);
    }
}

// ============================================================================
struct MainP {
    const float *input_pts, *input_views, *input_pls;
    const float *bias[9];          // pb0..7, feature_b
    const float *views_b;
    const float *alpha_w, *alpha_b;
    const float *rgb_w, *rgb_b;
    float* out;
};

extern __shared__ char smdyn[];

__global__ void __launch_bounds__(NTH, 2) nerf_hmma(MainP P) {
    char* sm = smdyn;
    const uint32_t base32 = smem_u32(sm);
    const int tid = threadIdx.x, lane = tid & 31, wid = tid >> 5;
    const int wn = wid >> 1, wm = wid & 1;      // group=wn: warps 2wn, 2wn+1
    const bool loader = (wm == 0);
    const int barid = 1 + wn;
    const int blk = blockIdx.x;

    // prologue: loaders prefetch chunks 0 and 1 (bufs 0, 1)
    if (loader) {
        load_slice<8>(base32, wn, lane, 0, 0); cp_commit();
        load_slice<8>(base32, wn, lane, 1, 1); cp_commit();
    }

    // e_pts build: cols 0..83, pad 84..95 zero (64 rows)
    if (tid < 64) {
        size_t gidx = (size_t)blk * 64 + tid;
        float4 p4 = *reinterpret_cast<const float4*>(P.input_pts + gidx * 4);
        float xs[4] = {p4.x, p4.y, p4.z, p4.w};
        float vals[96];
        #pragma unroll
        for (int d = 0; d < 4; d++) vals[d] = xs[d];
        #pragma unroll
        for (int d = 0; d < 4; d++) {
            float f = 1.f;
            #pragma unroll
            for (int l = 0; l < 10; l++) {
                float sn, cs; sincosf(xs[d] * f, &sn, &cs);
                vals[4 + d * 20 + l * 2]     = sn;
                vals[4 + d * 20 + l * 2 + 1] = cs;
                f *= 2.f;
            }
        }
        #pragma unroll
        for (int k = 84; k < 96; k++) vals[k] = 0.f;
        char* rh = sm + A_HI + (uint32_t)tid * ASTR;
        #pragma unroll 4
        for (int k = 0; k < 96; k += 2)
            *(uint32_t*)(rh + k * 2) = pack_h2(vals[k], vals[k + 1]);
    }
    __syncthreads();

    const int L_koff[9] = {0, 96, 96, 96, 96, 0, 96, 96, 96};
    const int L_nch[9]  = {3, 8, 8, 8, 8, 11, 8, 8, 8};
    float acc[2][8][4];
    int g = 0;

    #pragma unroll 1
    for (int l = 0; l < 9; l++) {
        #pragma unroll
        for (int mt = 0; mt < 2; mt++)
            #pragma unroll
            for (int n8 = 0; n8 < 8; n8++)
                #pragma unroll
                for (int q = 0; q < 4; q++) acc[mt][n8][q] = 0.f;

        const int koff = L_koff[l], nch = L_nch[l];
        #pragma unroll 1
        for (int ch = 0; ch < nch; ch++) {
            // iteration entry: group finished chunk g-1 -> buf (g-1)%3 == (g+2)%3 free
            named_bar(barid);
            if (loader) {
                if (g + 2 < NCHTOT) {
                    int b2 = (g + 2) % 3;
                    if (g + 2 >= 70) load_slice<4>(base32, wn, lane, g + 2, b2);
                    else             load_slice<8>(base32, wn, lane, g + 2, b2);
                }
                cp_commit();
                cp_wait2();                      // chunk g slice landed
            }
            named_bar(barid);                    // visible to group
            chunk_mma<8>(base32,
                         base32 + SLB + (uint32_t)wn * GRPSTR + (uint32_t)(g % 3) * BUFSTR,
                         wm, lane, koff + ch * 32, acc);
            g++;
        }
        __syncthreads();                         // all MMA reads of A done

        // ---- epilogue: bias (+relu) (+alpha) -> fp16 -> A plane --------------
        const bool relu = (l != 8);
        const uint32_t colbase = (l == 8) ? 0u : 96u;
        const float* bias = P.bias[l];
        float ap[2][2] = {{0.f, 0.f}, {0.f, 0.f}};
        #pragma unroll
        for (int mt = 0; mt < 2; mt++) {
            #pragma unroll
            for (int half = 0; half < 2; half++) {
                const uint32_t row = (uint32_t)(wm * 32 + mt * 16 + half * 8 + (lane >> 2));
                char* rh = sm + A_HI + row * ASTR + colbase * 2u;
                #pragma unroll
                for (int n8 = 0; n8 < 8; n8++) {
                    const int col = wn * 64 + n8 * 8 + (lane & 3) * 2;
                    float2 bv = *(const float2*)(bias + col);
                    float f0 = acc[mt][n8][half * 2]     + bv.x;
                    float f1 = acc[mt][n8][half * 2 + 1] + bv.y;
                    if (relu) { f0 = fmaxf(f0, 0.f); f1 = fmaxf(f1, 0.f); }
                    if (l == 7) {
                        float2 aw = *(const float2*)(P.alpha_w + col);
                        ap[mt][half] += f0 * aw.x + f1 * aw.y;
                    }
                    *(uint32_t*)(rh + col * 2) = pack_h2(f0, f1);
                }
            }
        }
        if (l == 7) {        // alpha partials -> A plane row pad
            #pragma unroll
            for (int mt = 0; mt < 2; mt++)
                #pragma unroll
                for (int half = 0; half < 2; half++) {
                    float v = ap[mt][half];
                    v += __shfl_xor_sync(0xffffffffu, v, 1);
                    v += __shfl_xor_sync(0xffffffffu, v, 2);
                    if ((lane & 3) == 0) {
                        uint32_t row = (uint32_t)(wm * 32 + mt * 16 + half * 8 + (lane >> 2));
                        *(float*)(sm + A_HI + row * ASTR + APAD + wn * 4) = v;
                    }
                }
            __syncthreads();
            if (tid < 64) {
                char* rp = sm + A_HI + (uint32_t)tid * ASTR + APAD;
                float a = P.alpha_b[0];
                #pragma unroll
                for (int w = 0; w < 4; w++) a += *(float*)(rp + w * 4);
                P.out[(size_t)blk * 64 + tid] = a;
            }
        }
        if (l == 8 && tid < 64) {    // e_view into cols 256..319 (310..319 zero)
            size_t gidx = (size_t)blk * 64 + tid;
            float xs[6];
            xs[0] = P.input_views[gidx * 3];     xs[1] = P.input_views[gidx * 3 + 1];
            xs[2] = P.input_views[gidx * 3 + 2]; xs[3] = P.input_pls[gidx * 3];
            xs[4] = P.input_pls[gidx * 3 + 1];   xs[5] = P.input_pls[gidx * 3 + 2];
            float vals[64];
            #pragma unroll
            for (int d = 0; d < 6; d++) vals[d] = xs[d];
            #pragma unroll
            for (int d = 0; d < 6; d++) {
                float f = 1.f;
                #pragma unroll
                for (int q = 0; q < 4; q++) {
                    float sn, cs; sincosf(xs[d] * f, &sn, &cs);
                    vals[6 + d * 8 + q * 2]     = sn;
                    vals[6 + d * 8 + q * 2 + 1] = cs;
                    f *= 2.f;
                }
            }
            #pragma unroll
            for (int k = 54; k < 64; k++) vals[k] = 0.f;
            char* rh = sm + A_HI + (uint32_t)tid * ASTR + 256u * 2u;
            #pragma unroll 4
            for (int k = 0; k < 64; k += 2)
                *(uint32_t*)(rh + k * 2) = pack_h2(vals[k], vals[k + 1]);
        }
        __syncthreads();                         // A rewrite visible to all
    }

    // ---- views layer: K=320, N=128 (10 chunks) --------------------------------
    #pragma unroll
    for (int mt = 0; mt < 2; mt++)
        #pragma unroll
        for (int n8 = 0; n8 < 8; n8++)
            #pragma unroll
            for (int q = 0; q < 4; q++) acc[mt][n8][q] = 0.f;
    #pragma unroll 1
    for (int ch = 0; ch < 10; ch++) {
        named_bar(barid);
        if (loader) {
            if (g + 2 < NCHTOT) load_slice<4>(base32, wn, lane, g + 2, (g + 2) % 3);
            cp_commit();
            cp_wait2();
        }
        named_bar(barid);
        chunk_mma<4>(base32,
                     base32 + SLB + (uint32_t)wn * GRPSTR + (uint32_t)(g % 3) * BUFSTR,
                     wm, lane, ch * 32, acc);
        g++;
    }
    __syncthreads();

    // ---- rgb head: relu(C + views_b) . rgb_w, fp32 ----------------------------
    float rp[2][2][3] = {};
    #pragma unroll
    for (int mt = 0; mt < 2; mt++)
        #pragma unroll
        for (int half = 0; half < 2; half++)
            #pragma unroll
            for (int n8 = 0; n8 < 4; n8++) {
                const int col = wn * 32 + n8 * 8 + (lane & 3) * 2;
                float f0 = fmaxf(acc[mt][n8][half * 2]     + P.views_b[col],     0.f);
                float f1 = fmaxf(acc[mt][n8][half * 2 + 1] + P.views_b[col + 1], 0.f);
                const float* w0 = P.rgb_w + (size_t)col * 3;
                #pragma unroll
                for (int k = 0; k < 3; k++)
                    rp[mt][half][k] += f0 * w0[k] + f1 * w0[3 + k];
            }
    #pragma unroll
    for (int mt = 0; mt < 2; mt++)
        #pragma unroll
        for (int half = 0; half < 2; half++) {
            #pragma unroll
            for (int k = 0; k < 3; k++) {
                float v = rp[mt][half][k];
                v += __shfl_xor_sync(0xffffffffu, v, 1);
                v += __shfl_xor_sync(0xffffffffu, v, 2);
                rp[mt][half][k] = v;
            }
            if ((lane & 3) == 0) {
                uint32_t row = (uint32_t)(wm * 32 + mt * 16 + half * 8 + (lane >> 2));
                char* p = sm + PRGB + (row * 4 + wn) * 12;
                #pragma unroll
                for (int k = 0; k < 3; k++) *(float*)(p + k * 4) = rp[mt][half][k];
            }
        }
    __syncthreads();
    if (tid < 64) {
        float r[3] = {P.rgb_b[0], P.rgb_b[1], P.rgb_b[2]};
        char* p = sm + PRGB + (uint32_t)tid * 48;
        #pragma unroll
        for (int w = 0; w < 4; w++)
            #pragma unroll
            for (int k = 0; k < 3; k++) r[k] += *(float*)(p + w * 12 + k * 4);
        size_t gidx = (size_t)blk * 64 + tid;
        #pragma unroll
        for (int k = 0; k < 3; k++) P.out[(size_t)NPTS + gidx * 3 + k] = r[k];
    }
}

// ============================================================================
extern "C" void kernel_launch(void* const* d_in, const int* in_sizes, int n_in,
                              void* d_out, int out_size)
{
    (void)in_sizes; (void)n_in; (void)out_size;

    PrepP pp;
    for (int i = 0; i < 8; i++) pp.w[i] = (const float*)d_in[3 + 2 * i];
    pp.w[8] = (const float*)d_in[21];     // feature_w
    pp.w[9] = (const float*)d_in[19];     // views_w

    MainP P;
    P.input_pts   = (const float*)d_in[0];
    P.input_views = (const float*)d_in[1];
    P.input_pls   = (const float*)d_in[2];
    for (int i = 0; i < 8; i++) P.bias[i] = (const float*)d_in[4 + 2 * i];
    P.bias[8]  = (const float*)d_in[22];  // feature_b
    P.views_b  = (const float*)d_in[20];
    P.alpha_w  = (const float*)d_in[23];
    P.alpha_b  = (const float*)d_in[24];
    P.rgb_w    = (const float*)d_in[25];
    P.rgb_b    = (const float*)d_in[26];
    P.out      = (float*)d_out;

    prep_kernel<<<1320, 512>>>(pp);

    cudaFuncSetAttribute(nerf_hmma, cudaFuncAttributeMaxDynamicSharedMemorySize, SMEM_REQ);
    nerf_hmma<<<NBLK, NTH, SMEM_REQ>>>(P);
}